// round 7
// baseline (speedup 1.0000x reference)
#include <cuda_runtime.h>

#define NB 8
#define PP 2048
#define DD 64
#define EPSI 1e-3f
#define KK 1442.69504089f        /* 1000 * log2(e) */
#define INVKK 6.9314718056e-4f   /* 1/KK = ln2/1000 */
#define EL2 6.9314718056e-4f     /* ln2 / 1000 */
#define L2E 1.44269504089f
#define NPb (NB*PP)

__device__ __align__(256) float g_C[(size_t)NB * PP * PP]; // 134 MB cost matrix
__device__ __align__(256) float g_An[NPb * DD];
__device__ __align__(256) float g_Bn[NPb * DD];
__device__ __align__(256) float g_rs[NPb];
__device__ __align__(256) float g_cs[NPb];
__device__ __align__(256) float g_lmu[NPb];
__device__ __align__(256) float g_lnu[NPb];
__device__ __align__(256) float g_u[NPb];
__device__ __align__(256) float g_v[NPb];
__device__ __align__(256) float g_pm[NB * 16 * PP];   // col partial max (log2 units)
__device__ __align__(256) float g_ps[NB * 16 * PP];   // col partial sum
__device__ __align__(256) float g_pt[NB * 16 * PP];   // col partial pi*C sum
__device__ __align__(256) float g_TS[NPb];            // per-col (nu+1e-8)*T/S
__device__ float g_errsum[16];
__device__ int g_flag;

// ---------------- block sum reduction (256 threads) ------------------------
__device__ __forceinline__ float block_sum256(float v, float* red) {
    __syncthreads();
    #pragma unroll
    for (int off = 16; off; off >>= 1) v += __shfl_xor_sync(0xffffffffu, v, off);
    int w = threadIdx.x >> 5, l = threadIdx.x & 31;
    if (l == 0) red[w] = v;
    __syncthreads();
    if (threadIdx.x < 32) {
        float x = (l < 8) ? red[l] : 0.0f;
        #pragma unroll
        for (int off = 4; off; off >>= 1) x += __shfl_xor_sync(0xffffffffu, x, off);
        if (l == 0) red[32] = x;
    }
    __syncthreads();
    return red[32];
}

// ---------------- prep: normalize inputs, zero state -----------------------
__global__ __launch_bounds__(256) void k_prep(const float* __restrict__ a,
                                              const float* __restrict__ b,
                                              float* __restrict__ out) {
    int idx = blockIdx.x * 256 + threadIdx.x;          // 0..16383
    {
        const float4* s = (const float4*)(a + (size_t)idx * DD);
        float nrm = 0.0f;
        #pragma unroll
        for (int q = 0; q < 16; q++) {
            float4 t = s[q];
            nrm += t.x * t.x + t.y * t.y + t.z * t.z + t.w * t.w;
        }
        float sc = 1.0f / fmaxf(sqrtf(nrm), 1e-12f);
        float4* d = (float4*)(g_An + (size_t)idx * DD);
        #pragma unroll
        for (int q = 0; q < 16; q++) {
            float4 t = s[q];
            t.x *= sc; t.y *= sc; t.z *= sc; t.w *= sc;
            d[q] = t;
        }
    }
    {
        const float4* s = (const float4*)(b + (size_t)idx * DD);
        float nrm = 0.0f;
        #pragma unroll
        for (int q = 0; q < 16; q++) {
            float4 t = s[q];
            nrm += t.x * t.x + t.y * t.y + t.z * t.z + t.w * t.w;
        }
        float sc = 1.0f / fmaxf(sqrtf(nrm), 1e-12f);
        float4* d = (float4*)(g_Bn + (size_t)idx * DD);
        #pragma unroll
        for (int q = 0; q < 16; q++) {
            float4 t = s[q];
            t.x *= sc; t.y *= sc; t.z *= sc; t.w *= sc;
            d[q] = t;
        }
    }
    g_u[idx] = 0.0f; g_v[idx] = 0.0f; g_rs[idx] = 0.0f; g_cs[idx] = 0.0f;
    if (idx < NB) out[idx] = 0.0f;
    if (idx < 16) g_errsum[idx] = 0.0f;
    if (idx == 0) g_flag = 0;
}

// ---------------- GEMM: C = 1 - Ahat . Bhat^T, fused S row/col sums --------
__global__ __launch_bounds__(256) void k_gemm() {
    __shared__ float As[128][33];
    __shared__ float Bs[32][132];
    int b = blockIdx.z;
    int row0 = blockIdx.y * 128, col0 = blockIdx.x * 128;
    const float* Ab = g_An + (size_t)b * PP * DD;
    const float* Bb = g_Bn + (size_t)b * PP * DD;
    int t = threadIdx.x, tx = t & 15, ty = t >> 4;

    unsigned long long acc[8][4];
    #pragma unroll
    for (int i = 0; i < 8; i++)
        #pragma unroll
        for (int j = 0; j < 4; j++) acc[i][j] = 0ULL;

    #pragma unroll
    for (int kp = 0; kp < 2; kp++) {
        __syncthreads();
        int kq = t & 7, rq = t >> 3;
        #pragma unroll
        for (int p = 0; p < 4; p++) {
            int r = p * 32 + rq;
            float4 v = *(const float4*)(Ab + (size_t)(row0 + r) * DD + kp * 32 + kq * 4);
            As[r][kq * 4 + 0] = v.x; As[r][kq * 4 + 1] = v.y;
            As[r][kq * 4 + 2] = v.z; As[r][kq * 4 + 3] = v.w;
            float4 w = *(const float4*)(Bb + (size_t)(col0 + r) * DD + kp * 32 + kq * 4);
            Bs[kq * 4 + 0][r] = w.x; Bs[kq * 4 + 1][r] = w.y;
            Bs[kq * 4 + 2][r] = w.z; Bs[kq * 4 + 3][r] = w.w;
        }
        __syncthreads();
        #pragma unroll 4
        for (int k = 0; k < 32; k++) {
            union { float4 f; unsigned long long u[2]; } b0, b1;
            b0.f = *(const float4*)&Bs[k][tx * 4];
            b1.f = *(const float4*)&Bs[k][64 + tx * 4];
            #pragma unroll
            for (int i = 0; i < 8; i++) {
                unsigned int ai = __float_as_uint(As[ty * 8 + i][k]);
                unsigned long long a2;
                asm("mov.b64 %0, {%1, %1};" : "=l"(a2) : "r"(ai));
                asm("fma.rn.f32x2 %0, %1, %2, %0;" : "+l"(acc[i][0]) : "l"(a2), "l"(b0.u[0]));
                asm("fma.rn.f32x2 %0, %1, %2, %0;" : "+l"(acc[i][1]) : "l"(a2), "l"(b0.u[1]));
                asm("fma.rn.f32x2 %0, %1, %2, %0;" : "+l"(acc[i][2]) : "l"(a2), "l"(b1.u[0]));
                asm("fma.rn.f32x2 %0, %1, %2, %0;" : "+l"(acc[i][3]) : "l"(a2), "l"(b1.u[1]));
            }
        }
    }
    __syncthreads();

    float rs[8], cs8[8];
    #pragma unroll
    for (int j = 0; j < 8; j++) cs8[j] = 0.0f;
    #pragma unroll
    for (int i = 0; i < 8; i++) {
        float vals[8];
        #pragma unroll
        for (int jp = 0; jp < 4; jp++) {
            union { unsigned long long u; float2 f; } cv; cv.u = acc[i][jp];
            vals[jp * 2 + 0] = cv.f.x;
            vals[jp * 2 + 1] = cv.f.y;
        }
        size_t base = ((size_t)b * PP + row0 + ty * 8 + i) * (size_t)PP + col0;
        *(float4*)(g_C + base + tx * 4) =
            make_float4(1.0f - vals[0], 1.0f - vals[1], 1.0f - vals[2], 1.0f - vals[3]);
        *(float4*)(g_C + base + 64 + tx * 4) =
            make_float4(1.0f - vals[4], 1.0f - vals[5], 1.0f - vals[6], 1.0f - vals[7]);
        float rsum = 0.0f;
        #pragma unroll
        for (int j = 0; j < 8; j++) { rsum += vals[j]; cs8[j] += vals[j]; }
        rs[i] = rsum;
    }
    float* red = (float*)As;
    #pragma unroll
    for (int i = 0; i < 8; i++) red[(ty * 8 + i) * 16 + tx] = rs[i];
    __syncthreads();
    if (t < 128) {
        float s = 0.0f;
        #pragma unroll
        for (int q = 0; q < 16; q++) s += red[t * 16 + q];
        atomicAdd(&g_rs[b * PP + row0 + t], s);
    }
    __syncthreads();
    #pragma unroll
    for (int j = 0; j < 8; j++) {
        int cc = (j < 4) ? (tx * 4 + j) : (64 + tx * 4 + (j - 4));
        red[cc * 16 + ty] = cs8[j];
    }
    __syncthreads();
    if (t < 128) {
        float s = 0.0f;
        #pragma unroll
        for (int q = 0; q < 16; q++) s += red[t * 16 + q];
        atomicAdd(&g_cs[b * PP + col0 + t], s);
    }
}

// ---------------- weights -> log(mu+1e-8) ----------------------------------
__device__ __forceinline__ void wproc(const float* __restrict__ sum,
                                      float* __restrict__ out, float* red, int t) {
    float raw[8], s = 0.0f;
    #pragma unroll
    for (int q = 0; q < 8; q++) {
        raw[q] = sum[t + 256 * q] * (1.0f / PP);
        s += fabsf(raw[q]);
    }
    s = block_sum256(s, red);
    float inv1 = 1.0f / fmaxf(s, 1e-12f);
    float c[8]; float s2 = 0.0f;
    #pragma unroll
    for (int q = 0; q < 8; q++) { c[q] = fmaxf(raw[q] * inv1, 0.0f); s2 += fabsf(c[q]); }
    s2 = block_sum256(s2, red);
    float inv2 = 1.0f / fmaxf(s2, 1e-12f);
    #pragma unroll
    for (int q = 0; q < 8; q++) out[t + 256 * q] = logf(c[q] * inv2 + 1e-8f);
}

__global__ __launch_bounds__(256) void k_weights() {
    __shared__ float red[40];
    int b = blockIdx.x, t = threadIdx.x;
    wproc(g_rs + b * PP, g_lmu + b * PP, red, t);
    wproc(g_cs + b * PP, g_lnu + b * PP, red, t);
}

// ---- row pass (REVERSE sweep): quarter-row per warp, 2 rows per block -----
__global__ __launch_bounds__(256) void k_row(int it) {
    if (g_flag) return;
    __shared__ float vs[2048];          // v * KK
    __shared__ float wm[8], ws[8];
    __shared__ float erw[2];
    int t = threadIdx.x, l = t & 31, w = t >> 5;
    int g = 8191 - blockIdx.x;          // REVERSE block mapping (serpentine)
    int b = g >> 10;
    const float4* vsrc = (const float4*)(g_v + (b << 11));
    #pragma unroll
    for (int q = 0; q < 2; q++) {
        float4 v4 = vsrc[t + q * 256];
        ((float4*)vs)[t + q * 256] = make_float4(v4.x * KK, v4.y * KK, v4.z * KK, v4.w * KK);
    }
    __syncthreads();
    int rl = w >> 2, qq = w & 3;        // row-in-block, quarter
    int bi = (b << 11) + ((g & 1023) << 1) + rl;
    const float* Crow = g_C + ((size_t)bi << 11) + (qq << 9);
    const float* vh = vs + (qq << 9);

    float x[16];
    #pragma unroll
    for (int k = 0; k < 4; k++) {
        float4 c = *(const float4*)(Crow + k * 128 + l * 4);
        float4 vv = *(const float4*)(vh + k * 128 + l * 4);
        x[k * 4 + 0] = fmaf(c.x, -KK, vv.x);
        x[k * 4 + 1] = fmaf(c.y, -KK, vv.y);
        x[k * 4 + 2] = fmaf(c.z, -KK, vv.z);
        x[k * 4 + 3] = fmaf(c.w, -KK, vv.w);
    }
    float mk[4];
    #pragma unroll
    for (int k = 0; k < 4; k++)
        mk[k] = fmaxf(fmaxf(x[k*4], x[k*4+1]), fmaxf(x[k*4+2], x[k*4+3]));
    float m = fmaxf(fmaxf(mk[0], mk[1]), fmaxf(mk[2], mk[3]));
    #pragma unroll
    for (int off = 16; off; off >>= 1) m = fmaxf(m, __shfl_xor_sync(0xffffffffu, m, off));
    float s0 = 0.0f, s1 = 0.0f, s2 = 0.0f, s3 = 0.0f;
    #pragma unroll
    for (int k = 0; k < 4; k++) {
        s0 += exp2f(x[k * 4 + 0] - m);
        s1 += exp2f(x[k * 4 + 1] - m);
        s2 += exp2f(x[k * 4 + 2] - m);
        s3 += exp2f(x[k * 4 + 3] - m);
    }
    float s = (s0 + s1) + (s2 + s3);
    #pragma unroll
    for (int off = 16; off; off >>= 1) s += __shfl_xor_sync(0xffffffffu, s, off);
    if (l == 0) { wm[w] = m; ws[w] = s; }
    __syncthreads();
    if (t < 2) {
        float M = fmaxf(fmaxf(wm[t*4], wm[t*4+1]), fmaxf(wm[t*4+2], wm[t*4+3]));
        float S = ws[t*4]   * exp2f(wm[t*4]   - M) + ws[t*4+1] * exp2f(wm[t*4+1] - M)
                + ws[t*4+2] * exp2f(wm[t*4+2] - M) + ws[t*4+3] * exp2f(wm[t*4+3] - M);
        int bi2 = (b << 11) + ((g & 1023) << 1) + t;
        float un = EPSI * g_lmu[bi2] - EL2 * (M + __log2f(S));
        erw[t] = fabsf(un - g_u[bi2]);
        g_u[bi2] = un;
    }
    __syncthreads();
    if (t == 0) atomicAdd(&g_errsum[it], erw[0] + erw[1]);
}

// ---- col pass partials (FORWARD sweep) + fused pi*C accumulation ----------
// per element: x = (u_i - C_ij)*KK ; e = exp2(x - m); S += e; and for the
// output, T += e*C with C = (uK - x)/KK -> T = (A - B)/KK, A=sum e*uK, B=sum e*x
__global__ __launch_bounds__(256) void k_col() {
    if (g_flag) return;
    __shared__ float us[128];           // u * KK
    int blk = blockIdx.x;               // 1024 = b(8) x chunk(16) x tile(8), fwd
    int b = blk >> 7;
    int chunk = (blk >> 3) & 15;
    int tile = blk & 7;
    int t = threadIdx.x;
    int j = (tile << 8) + t;
    int r0 = chunk << 7;
    if (t < 128) us[t] = g_u[(b << 11) + r0 + t] * KK;
    __syncthreads();
    const float* Cb = g_C + ((size_t)b << 22) + ((size_t)r0 << 11) + j;
    float m = -3.0e38f;
    float s0 = 0.0f, s1 = 0.0f, s2 = 0.0f, s3 = 0.0f;
    float A0 = 0.0f, A1 = 0.0f, B0 = 0.0f, B1 = 0.0f;
    #pragma unroll 1
    for (int g = 0; g < 8; g++) {
        float c[16];
        #pragma unroll
        for (int q = 0; q < 16; q++) c[q] = Cb[(size_t)q << 11];
        Cb += (size_t)16 << 11;
        float x[16];
        #pragma unroll
        for (int q = 0; q < 16; q++) x[q] = fmaf(c[q], -KK, us[g * 16 + q]);
        float m01 = fmaxf(fmaxf(x[0], x[1]), fmaxf(x[2], x[3]));
        float m23 = fmaxf(fmaxf(x[4], x[5]), fmaxf(x[6], x[7]));
        float m45 = fmaxf(fmaxf(x[8], x[9]), fmaxf(x[10], x[11]));
        float m67 = fmaxf(fmaxf(x[12], x[13]), fmaxf(x[14], x[15]));
        float lm = fmaxf(fmaxf(m01, m23), fmaxf(m45, m67));
        float mn = fmaxf(m, lm);
        float sc = exp2f(m - mn);
        s0 *= sc; s1 *= sc; s2 *= sc; s3 *= sc;
        A0 *= sc; A1 *= sc; B0 *= sc; B1 *= sc;
        #pragma unroll
        for (int q = 0; q < 16; q += 4) {
            float e0 = exp2f(x[q + 0] - mn);
            float e1 = exp2f(x[q + 1] - mn);
            float e2 = exp2f(x[q + 2] - mn);
            float e3 = exp2f(x[q + 3] - mn);
            s0 += e0; s1 += e1; s2 += e2; s3 += e3;
            A0 = fmaf(e0, us[g * 16 + q + 0], A0);
            A1 = fmaf(e1, us[g * 16 + q + 1], A1);
            A0 = fmaf(e2, us[g * 16 + q + 2], A0);
            A1 = fmaf(e3, us[g * 16 + q + 3], A1);
            B0 = fmaf(e0, x[q + 0], B0);
            B1 = fmaf(e1, x[q + 1], B1);
            B0 = fmaf(e2, x[q + 2], B0);
            B1 = fmaf(e3, x[q + 3], B1);
        }
        m = mn;
    }
    float s = (s0 + s1) + (s2 + s3);
    float T = ((A0 + A1) - (B0 + B1)) * INVKK;
    int pidx = (((b << 4) + chunk) << 11) + j;
    g_pm[pidx] = m;
    g_ps[pidx] = s;
    g_pt[pidx] = T;
}

// ---- combine col partials -> v, per-col output contrib; early-stop flag ---
__global__ __launch_bounds__(256) void k_combine(int it) {
    if (g_flag) return;
    int t = blockIdx.x * 256 + threadIdx.x;     // 16384 = b*2048 + j
    int b = t >> 11, j = t & 2047;
    int base = (b << 4);
    float M = -3.0e38f;
    #pragma unroll
    for (int ch = 0; ch < 16; ch++)
        M = fmaxf(M, g_pm[((base + ch) << 11) + j]);
    float S = 0.0f, T = 0.0f;
    #pragma unroll
    for (int ch = 0; ch < 16; ch++) {
        float w = exp2f(g_pm[((base + ch) << 11) + j] - M);
        S = fmaf(g_ps[((base + ch) << 11) + j], w, S);
        T = fmaf(g_pt[((base + ch) << 11) + j], w, T);
    }
    float lnu = g_lnu[t];
    g_v[t] = EPSI * lnu - EL2 * (M + __log2f(S));
    g_TS[t] = exp2f(L2E * lnu) * T / S;     // (nu+1e-8) * T / S
    if (t == 0) {
        // err = sum(|du|)/NB < 0.1  <=>  errsum < 0.8 (k_row fully retired)
        if (g_errsum[it] < 0.1f * NB) g_flag = 1;
    }
}

// ---- output: out[b] = sum_j g_TS[b][j]  (from last executed iteration) ----
__global__ __launch_bounds__(256) void k_out(float* __restrict__ out) {
    __shared__ float red[40];
    int b = blockIdx.x, t = threadIdx.x;
    float s = 0.0f;
    #pragma unroll
    for (int q = 0; q < 8; q++) s += g_TS[(b << 11) + t + 256 * q];
    s = block_sum256(s, red);
    if (t == 0) out[b] = s;
}

extern "C" void kernel_launch(void* const* d_in, const int* in_sizes, int n_in,
                              void* d_out, int out_size) {
    const float* a = (const float*)d_in[0];
    const float* b = (const float*)d_in[1];
    float* out = (float*)d_out;
    k_prep<<<64, 256>>>(a, b, out);
    dim3 gg(16, 16, NB);
    k_gemm<<<gg, 256>>>();
    k_weights<<<NB, 256>>>();
    for (int it = 0; it < 10; it++) {
        k_row<<<8192, 256>>>(it);
        k_col<<<1024, 256>>>();
        k_combine<<<64, 256>>>(it);
    }
    k_out<<<NB, 256>>>(out);
}